// round 2
// baseline (speedup 1.0000x reference)
#include <cuda_runtime.h>
#include <cuda_bf16.h>
#include <stdint.h>

// Problem constants
#define DIMS   128          // embedding dim (C)
#define KCODES 512          // num embeddings
#define NB     32           // batch
#define HW     4096         // 64*64
#define NROWS  131072       // NB*HW
#define ZSTRB  524288       // DIMS*HW (per-batch stride in z)

// Output layout (floats, concatenated tuple)
#define OFF_Q    ((size_t)0)
#define OFF_LOSS ((size_t)16777216)
#define OFF_IDX  ((size_t)16777217)
#define OFF_EMB  ((size_t)16908289)
#define OFF_CS   ((size_t)16973825)
#define OFF_EA   ((size_t)16974337)

// Main kernel tiling
#define MTILE   128         // rows per block
#define KCHUNK  256         // codes per shared chunk (2 chunks)
#define SMEM_MAIN (65536 + 131072 + 1024 + 1024 + 512)  // xs + es + enorm + minbuf + idxs

// Device scratch (static allocation — allowed)
__device__ float g_embed_sum[DIMS * KCODES];
__device__ int   g_counts[KCODES];
__device__ float g_loss;
__device__ float g_enorm[KCODES];
__device__ float g_cs[KCODES];
__device__ int   g_idx[NROWS];

// ---------- helpers ----------
__device__ __forceinline__ unsigned fenc(float f) {
    unsigned u = __float_as_uint(f);
    return (u & 0x80000000u) ? ~u : (u | 0x80000000u);
}
__device__ __forceinline__ float fdec(unsigned e) {
    return (e & 0x80000000u) ? __uint_as_float(e ^ 0x80000000u)
                             : __uint_as_float(~e);
}
__device__ __forceinline__ void unpack2(unsigned long long v, float& lo, float& hi) {
    asm("mov.b64 {%0,%1}, %2;" : "=f"(lo), "=f"(hi) : "l"(v));
}

// ---------- K0: zero scratch ----------
__global__ void k_zero() {
    int i = blockIdx.x * 256 + threadIdx.x;          // grid 256 x 256 = 65536
    g_embed_sum[i] = 0.f;
    if (i < KCODES) g_counts[i] = 0;
    if (i == 0) g_loss = 0.f;
}

// ---------- K0b: per-code squared norms ----------
__global__ void k_enorm(const float* __restrict__ emb) {
    int k = blockIdx.x * 256 + threadIdx.x;          // grid 2 x 256 = 512
    float s = 0.f;
    #pragma unroll 8
    for (int d = 0; d < DIMS; d++) {
        float e = emb[d * KCODES + k];               // coalesced over k
        s = fmaf(e, e, s);
    }
    g_enorm[k] = s;
}

// ---------- K1: fused distance GEMM + argmin + gather + loss + histogram ----------
__global__ __launch_bounds__(256, 1)
void k_main(const float* __restrict__ z, const float* __restrict__ emb,
            float* __restrict__ out) {
    extern __shared__ float sm[];
    float* xs   = sm;                                  // [128][128]  64 KB
    float* es   = sm + 16384;                          // [128][256] 128 KB
    float* en_s = es + 32768;                          // [256]
    unsigned long long* minbuf = (unsigned long long*)(en_s + 256);  // [128]
    int* idxs = (int*)(minbuf + 128);                  // [128]
    __shared__ float lbuf;

    const int tid = threadIdx.x;
    const int tr = tid & 15;        // row group  (rows tr + 16*jr, jr=0..7)
    const int tc = tid >> 4;        // code group (codes 2*tc + 32*jc (+1), jc=0..7)
    const int blk = blockIdx.x;
    const int b  = blk >> 5;
    const int s0 = (blk & 31) << 7;

    const float* zb = z + (size_t)b * ZSTRB + s0;
    // load x tile [d][r]
    for (int i = tid; i < 16384; i += 256) {
        int d = i >> 7, r = i & 127;
        xs[i] = zb[(size_t)d * HW + r];
    }
    if (tid < 128) minbuf[tid] = 0xFFFFFFFFFFFFFFFFULL;
    if (tid == 0)  lbuf = 0.f;

    const float* xcol = xs + tr;
    const float* ecol = es + 2 * tc;

    for (int c = 0; c < 2; ++c) {
        __syncthreads();
        const int kc0 = c << 8;
        for (int i = tid; i < 32768; i += 256) {
            int d = i >> 8, kk = i & 255;
            es[i] = emb[d * KCODES + kc0 + kk];
        }
        en_s[tid] = g_enorm[kc0 + tid];
        __syncthreads();

        unsigned long long acc[8][8];
        #pragma unroll
        for (int jr = 0; jr < 8; jr++)
            #pragma unroll
            for (int jc = 0; jc < 8; jc++) acc[jr][jc] = 0ULL;

        #pragma unroll 2
        for (int d = 0; d < DIMS; ++d) {
            unsigned long long xv[8], ev[8];
            #pragma unroll
            for (int jr = 0; jr < 8; jr++) {
                float x = xcol[d * 128 + 16 * jr];
                asm("mov.b64 %0, {%1,%1};" : "=l"(xv[jr]) : "f"(x));
            }
            #pragma unroll
            for (int jc = 0; jc < 8; jc++)
                ev[jc] = *reinterpret_cast<const unsigned long long*>(&ecol[d * 256 + 32 * jc]);
            #pragma unroll
            for (int jr = 0; jr < 8; jr++)
                #pragma unroll
                for (int jc = 0; jc < 8; jc++)
                    asm("fma.rn.f32x2 %0, %1, %2, %0;"
                        : "+l"(acc[jr][jc]) : "l"(xv[jr]), "l"(ev[jc]));
        }

        // per-thread argmin over its 16 codes, then shared atomicMin per row
        #pragma unroll
        for (int jr = 0; jr < 8; jr++) {
            unsigned long long bkey = 0xFFFFFFFFFFFFFFFFULL;
            #pragma unroll
            for (int jc = 0; jc < 8; jc++) {
                float d0, d1;
                unpack2(acc[jr][jc], d0, d1);
                float e0 = en_s[2 * tc + 32 * jc];
                float e1 = en_s[2 * tc + 32 * jc + 1];
                float dist0 = fmaf(-2.f, d0, e0);
                float dist1 = fmaf(-2.f, d1, e1);
                unsigned c0 = (unsigned)(kc0 + 2 * tc + 32 * jc);
                unsigned long long k0 = ((unsigned long long)fenc(dist0) << 32) | c0;
                unsigned long long k1 = ((unsigned long long)fenc(dist1) << 32) | (c0 + 1u);
                unsigned long long kk = k0 < k1 ? k0 : k1;
                if (kk < bkey) bkey = kk;
            }
            atomicMin(&minbuf[tr + 16 * jr], bkey);
        }
    }
    __syncthreads();

    // per-row epilogue: decode argmin, loss, index outputs, histogram
    if (tid < 128) {
        unsigned long long key = minbuf[tid];
        int code = (int)(key & 0xFFFFFFFFu);
        float dmin = fdec((unsigned)(key >> 32));
        float xn = 0.f;
        #pragma unroll 8
        for (int d = 0; d < DIMS; d++) {
            float v = xs[d * 128 + tid];
            xn = fmaf(v, v, xn);
        }
        atomicAdd(&lbuf, xn + dmin);          // ||x-e||^2 via expansion
        idxs[tid] = code;
        int ng = blk * MTILE + tid;
        out[OFF_IDX + ng] = (float)code;
        g_idx[ng] = code;
        atomicAdd(&g_counts[code], 1);
    }
    __syncthreads();
    if (tid == 0) atomicAdd(&g_loss, lbuf);

    // gather quantized and write back in [B,D,H,W] layout (coalesced over r)
    for (int i = tid; i < 16384; i += 256) {
        int d = i >> 7, r = i & 127;
        out[OFF_Q + (size_t)b * ZSTRB + (size_t)d * HW + s0 + r] =
            emb[d * KCODES + idxs[r]];
    }
}

// ---------- K2: cluster-size EMA + Laplace smoothing ----------
__global__ void k_stats(const float* __restrict__ cs_in, float* __restrict__ out) {
    __shared__ float sh[KCODES];
    int k = threadIdx.x;                              // 512 threads
    float ncs = cs_in[k] * 0.99f + 0.01f * (float)g_counts[k];
    out[OFF_CS + k] = ncs;
    sh[k] = ncs;
    __syncthreads();
    for (int s = 256; s > 0; s >>= 1) {
        if (k < s) sh[k] += sh[k + s];
        __syncthreads();
    }
    float n = fmaxf(sh[0], 1e-5f);
    float c = (ncs + 1e-5f) / (n + KCODES * 1e-5f) * n;
    g_cs[k] = c;
}

// ---------- K4: embed_sum via d-plane pass with shared privatized bins ----------
__global__ void k_esum(const float* __restrict__ z) {
    __shared__ float accs[KCODES];
    const int d = blockIdx.x;       // 0..127
    const int c = blockIdx.y;       // 0..31 (== batch index: 4096 rows each)
    const int tid = threadIdx.x;    // 256
    accs[tid] = 0.f;
    accs[tid + 256] = 0.f;
    __syncthreads();
    const float* zp = z + (size_t)c * ZSTRB + (size_t)d * HW;
    const int* ip = g_idx + c * HW;
    for (int i = tid; i < HW; i += 256)
        atomicAdd(&accs[ip[i]], zp[i]);               // z read coalesced
    __syncthreads();
    float v0 = accs[tid], v1 = accs[tid + 256];
    if (v0 != 0.f) atomicAdd(&g_embed_sum[d * KCODES + tid], v0);
    if (v1 != 0.f) atomicAdd(&g_embed_sum[d * KCODES + tid + 256], v1);
}

// ---------- K5: finalize embed_avg EMA, new embedding, loss ----------
__global__ void k_final(const float* __restrict__ ea_in, float* __restrict__ out) {
    int i = blockIdx.x * 256 + threadIdx.x;           // grid 256 x 256 = 65536
    float es = g_embed_sum[i];
    float ea = ea_in[i] * 0.99f + 0.01f * es;
    out[OFF_EA + i] = ea;
    out[OFF_EMB + i] = ea / g_cs[i & (KCODES - 1)];
    if (i == 0) out[OFF_LOSS] = 1.25f * g_loss * (1.f / 16777216.f);
}

extern "C" void kernel_launch(void* const* d_in, const int* in_sizes, int n_in,
                              void* d_out, int out_size) {
    const float* z   = (const float*)d_in[0];
    const float* emb = (const float*)d_in[1];
    const float* cs  = (const float*)d_in[2];
    const float* ea  = (const float*)d_in[3];
    float* out = (float*)d_out;

    cudaFuncSetAttribute(k_main, cudaFuncAttributeMaxDynamicSharedMemorySize, SMEM_MAIN);

    k_zero<<<256, 256>>>();
    k_enorm<<<2, 256>>>(emb);
    k_main<<<1024, 256, SMEM_MAIN>>>(z, emb, out);
    k_stats<<<1, 512>>>(cs, out);
    k_esum<<<dim3(128, 32), 256>>>(z);
    k_final<<<256, 256>>>(ea, out);
}

// round 4
// speedup vs baseline: 1.4117x; 1.4117x over previous
#include <cuda_runtime.h>
#include <cuda_fp16.h>
#include <stdint.h>

#define DIMS   128
#define KCODES 512
#define NB     32
#define HW     4096
#define NROWS  131072
#define ZSTRB  524288

#define OFF_Q    ((size_t)0)
#define OFF_LOSS ((size_t)16777216)
#define OFF_IDX  ((size_t)16777217)
#define OFF_EMB  ((size_t)16908289)
#define OFF_CS   ((size_t)16973825)
#define OFF_EA   ((size_t)16974337)

#define TAU 2e-3f

// ---------------- device scratch ----------------
__device__ __half g_Ah[NROWS * DIMS];        // z split hi, row-major [row][d]
__device__ __half g_Al[NROWS * DIMS];        // z split lo
__device__ __half g_Bh[KCODES * DIMS];       // emb split hi, [code][d]
__device__ __half g_Bl[KCODES * DIMS];
__device__ float g_xnorm[NROWS];
__device__ unsigned long long g_hb[2][NROWS];   // per-half best key
__device__ unsigned long long g_hs[2][NROWS];   // per-half second key
__device__ unsigned long long g_minkey[NROWS];
__device__ float g_embed_sum[DIMS * KCODES];
__device__ int   g_counts[KCODES];
__device__ float g_loss;
__device__ float g_enorm[KCODES];
__device__ float g_cs[KCODES];
__device__ int   g_idx[NROWS];
__device__ int   g_nfix;
__device__ int   g_fixlist[NROWS];

// ---------------- helpers ----------------
__device__ __forceinline__ unsigned fenc(float f) {
    unsigned u = __float_as_uint(f);
    return (u & 0x80000000u) ? ~u : (u | 0x80000000u);
}
__device__ __forceinline__ float fdec(unsigned e) {
    return (e & 0x80000000u) ? __uint_as_float(e ^ 0x80000000u)
                             : __uint_as_float(~e);
}
__device__ __forceinline__ void mma16816(float* d, const uint32_t* a, const uint32_t* b) {
    asm volatile(
        "mma.sync.aligned.m16n8k16.row.col.f32.f16.f16.f32 "
        "{%0,%1,%2,%3}, {%4,%5,%6,%7}, {%8,%9}, {%0,%1,%2,%3};"
        : "+f"(d[0]), "+f"(d[1]), "+f"(d[2]), "+f"(d[3])
        : "r"(a[0]), "r"(a[1]), "r"(a[2]), "r"(a[3]), "r"(b[0]), "r"(b[1]));
}

// ---------------- K: zero scratch ----------------
__global__ void k_zero() {
    int i = blockIdx.x * 256 + threadIdx.x;            // 256 x 256
    g_embed_sum[i] = 0.f;
    if (i < KCODES) g_counts[i] = 0;
    if (i == 0) { g_loss = 0.f; g_nfix = 0; }
}

// ---------------- K: split embedding to fp16 h/l ----------------
__global__ void k_bsplit(const float* __restrict__ emb) {
    int d = blockIdx.x;                                // 128
    int k = threadIdx.x;                               // 512
    float e = emb[d * KCODES + k];
    __half h = __float2half_rn(e);
    __half l = __float2half_rn(e - __half2float(h));
    size_t o = (size_t)k * DIMS + d;
    g_Bh[o] = h; g_Bl[o] = l;
}

__global__ void k_enorm(const float* __restrict__ emb) {
    int k = blockIdx.x * 256 + threadIdx.x;            // 2 x 256
    float s = 0.f;
    #pragma unroll 8
    for (int d = 0; d < DIMS; d++) {
        float e = emb[d * KCODES + k];
        s = fmaf(e, e, s);
    }
    g_enorm[k] = s;
}

// ---------------- K: split z (transpose to row-major) + xnorm ----------------
__global__ void k_asplit(const float* __restrict__ z) {
    extern __shared__ float sm[];                      // [128][129]
    const int tid = threadIdx.x;
    const int blk = blockIdx.x;                        // 1024
    const int b = blk >> 5, s0 = (blk & 31) << 7;
    const int row0 = blk * 128;
    const float* zb = z + (size_t)b * ZSTRB + s0;
    for (int i = tid; i < 16384; i += 256) {
        int d = i >> 7, r = i & 127;
        sm[d * 129 + r] = zb[(size_t)d * HW + r];
    }
    __syncthreads();
    for (int i = tid; i < 16384; i += 256) {
        int d = i & 127, r = i >> 7;
        float x = sm[d * 129 + r];
        __half h = __float2half_rn(x);
        __half l = __float2half_rn(x - __half2float(h));
        size_t o = (size_t)(row0 + r) * DIMS + d;
        g_Ah[o] = h; g_Al[o] = l;
    }
    if (tid < 128) {
        float s = 0.f;
        #pragma unroll 8
        for (int d = 0; d < DIMS; d++) {
            float v = sm[d * 129 + tid];
            s = fmaf(v, v, s);
        }
        g_xnorm[row0 + tid] = s;
    }
}

// ---------------- K: mma.sync GEMM + per-half top-2 ----------------
// shared layout (bytes): A tiles (2 splits x 128 rows x 272B) = 69632
//                        B tiles (2 splits x 256 rows x 272B) = 139264
//                        en[256] f32, sbest[128] u64, ssec[128] u64
#define APITCH 272
#define SA_OFF 0
#define SB_OFF 69632
#define EN_OFF 208896
#define SBEST  209920
#define SSEC   210944
#define SM_GEMM 211968

__global__ __launch_bounds__(512, 1)
void k_gemm() {
    extern __shared__ char smc[];
    const int tid = threadIdx.x;
    const int wid = tid >> 5, lane = tid & 31;
    const int g = lane >> 2, t = lane & 3;
    const int mtile = blockIdx.x >> 1;
    const int nh = blockIdx.x & 1;
    const int r0 = mtile * 128;
    const int mr = (wid & 3) * 32;                    // warp row base
    const int nc = (wid >> 2) * 64;                   // warp col base (local)

    float* en_s = (float*)(smc + EN_OFF);
    unsigned long long* sbest = (unsigned long long*)(smc + SBEST);
    unsigned long long* ssec  = (unsigned long long*)(smc + SSEC);

    // loads: A 2 splits x 128 rows x 16 chunks
    for (int i = tid; i < 4096; i += 512) {
        int sp = i >> 11, rem = i & 2047;
        int row = rem >> 4, c = rem & 15;
        const __half* src = (sp ? g_Al : g_Ah) + (size_t)(r0 + row) * DIMS + c * 8;
        *(uint4*)(smc + SA_OFF + sp * 34816 + row * APITCH + c * 16) = *(const uint4*)src;
    }
    // B: 2 splits x 256 codes x 16 chunks
    for (int i = tid; i < 8192; i += 512) {
        int sp = i >> 12, rem = i & 4095;
        int row = rem >> 4, c = rem & 15;
        const __half* src = (sp ? g_Bl : g_Bh) + (size_t)(nh * 256 + row) * DIMS + c * 8;
        *(uint4*)(smc + SB_OFF + sp * 69632 + row * APITCH + c * 16) = *(const uint4*)src;
    }
    if (tid < 256) en_s[tid] = g_enorm[nh * 256 + tid];
    if (tid < 128) { sbest[tid] = ~0ULL; ssec[tid] = ~0ULL; }
    __syncthreads();

    float acc[2][8][4];
    #pragma unroll
    for (int mt = 0; mt < 2; mt++)
        #pragma unroll
        for (int nt = 0; nt < 8; nt++)
            #pragma unroll
            for (int q = 0; q < 4; q++) acc[mt][nt][q] = 0.f;

    const char* Ah_p = smc + SA_OFF + (mr + g) * APITCH + t * 4;
    const char* Al_p = Ah_p + 34816;
    const char* Bh_p = smc + SB_OFF + (nc + g) * APITCH + t * 4;
    const char* Bl_p = Bh_p + 69632;

    #pragma unroll
    for (int ks = 0; ks < 8; ks++) {
        const int kb = ks * 32;
        uint32_t ah[2][4], bh[8][2];
        #pragma unroll
        for (int mt = 0; mt < 2; mt++)
            #pragma unroll
            for (int j = 0; j < 4; j++)
                ah[mt][j] = *(const uint32_t*)(Ah_p + mt * 16 * APITCH
                              + (j & 1) * 8 * APITCH + kb + (j >> 1) * 16);
        #pragma unroll
        for (int nt = 0; nt < 8; nt++) {
            bh[nt][0] = *(const uint32_t*)(Bh_p + nt * 8 * APITCH + kb);
            bh[nt][1] = *(const uint32_t*)(Bh_p + nt * 8 * APITCH + kb + 16);
        }
        #pragma unroll
        for (int mt = 0; mt < 2; mt++)
            #pragma unroll
            for (int nt = 0; nt < 8; nt++)
                mma16816(acc[mt][nt], ah[mt], bh[nt]);
        // Al x Bh
        uint32_t al[2][4];
        #pragma unroll
        for (int mt = 0; mt < 2; mt++)
            #pragma unroll
            for (int j = 0; j < 4; j++)
                al[mt][j] = *(const uint32_t*)(Al_p + mt * 16 * APITCH
                              + (j & 1) * 8 * APITCH + kb + (j >> 1) * 16);
        #pragma unroll
        for (int mt = 0; mt < 2; mt++)
            #pragma unroll
            for (int nt = 0; nt < 8; nt++)
                mma16816(acc[mt][nt], al[mt], bh[nt]);
        // Ah x Bl (reuse bh regs)
        #pragma unroll
        for (int nt = 0; nt < 8; nt++) {
            bh[nt][0] = *(const uint32_t*)(Bl_p + nt * 8 * APITCH + kb);
            bh[nt][1] = *(const uint32_t*)(Bl_p + nt * 8 * APITCH + kb + 16);
        }
        #pragma unroll
        for (int mt = 0; mt < 2; mt++)
            #pragma unroll
            for (int nt = 0; nt < 8; nt++)
                mma16816(acc[mt][nt], ah[mt], bh[nt]);
    }

    // epilogue: per-thread top-2 per row, then block top-2 per row
    unsigned long long tb[4], ts[4];
    #pragma unroll
    for (int rs = 0; rs < 4; rs++) {
        const int mt = rs >> 1, rh = rs & 1;
        unsigned long long best = ~0ULL, sec = ~0ULL;
        #pragma unroll
        for (int nt = 0; nt < 8; nt++)
            #pragma unroll
            for (int q = 0; q < 2; q++) {
                int col = nc + nt * 8 + t * 2 + q;
                float dist = fmaf(-2.f, acc[mt][nt][rh * 2 + q], en_s[col]);
                unsigned long long key =
                    ((unsigned long long)fenc(dist) << 32) | (unsigned)(nh * 256 + col);
                if (key < best) { sec = best; best = key; }
                else if (key < sec) sec = key;
            }
        tb[rs] = best; ts[rs] = sec;
        atomicMin(&sbest[mr + mt * 16 + g + rh * 8], best);
    }
    __syncthreads();
    #pragma unroll
    for (int rs = 0; rs < 4; rs++) {
        const int row = mr + (rs >> 1) * 16 + g + (rs & 1) * 8;
        unsigned long long cand = (tb[rs] == sbest[row]) ? ts[rs] : tb[rs];
        atomicMin(&ssec[row], cand);
    }
    __syncthreads();
    if (tid < 128) {
        g_hb[nh][r0 + tid] = sbest[tid];
        g_hs[nh][r0 + tid] = ssec[tid];
    }
}

// ---------------- K: combine halves, compute margin, flag close rows --------
__global__ void k_pick() {
    int i = blockIdx.x * 256 + threadIdx.x;            // 512 x 256
    unsigned long long b0 = g_hb[0][i], b1 = g_hb[1][i];
    unsigned long long s0 = g_hs[0][i], s1 = g_hs[1][i];
    unsigned long long gb = b0 < b1 ? b0 : b1;
    unsigned long long lb = b0 < b1 ? b1 : b0;
    unsigned long long ls = s0 < s1 ? s0 : s1;
    unsigned long long gs = ls < lb ? ls : lb;
    g_minkey[i] = gb;
    float margin = fdec((unsigned)(gs >> 32)) - fdec((unsigned)(gb >> 32));
    if (margin < TAU) {
        int j = atomicAdd(&g_nfix, 1);
        g_fixlist[j] = i;
    }
}

// ---------------- K: exact fp32 re-scan for flagged rows ----------------
__global__ void k_fixup(const float* __restrict__ z, const float* __restrict__ emb) {
    __shared__ float zr[DIMS];
    __shared__ unsigned long long sk;
    const int tid = threadIdx.x;                       // 512
    const int n = g_nfix;
    for (int i = blockIdx.x; i < n; i += gridDim.x) {
        const int row = g_fixlist[i];
        const int b = row >> 12, s = row & 4095;
        if (tid < DIMS) zr[tid] = z[(size_t)b * ZSTRB + (size_t)tid * HW + s];
        if (tid == 0) sk = ~0ULL;
        __syncthreads();
        float dot = 0.f;
        #pragma unroll 8
        for (int d = 0; d < DIMS; d++)
            dot = fmaf(zr[d], emb[d * KCODES + tid], dot);
        float dist = fmaf(-2.f, dot, g_enorm[tid]);
        unsigned long long key = ((unsigned long long)fenc(dist) << 32) | (unsigned)tid;
        atomicMin(&sk, key);
        __syncthreads();
        if (tid == 0) g_minkey[row] = sk;
        __syncthreads();
    }
}

// ---------------- K: decode keys -> idx, histogram, loss ----------------
__global__ void k_decode(float* __restrict__ out) {
    __shared__ float red[256];
    __shared__ int hist[KCODES];
    const int tid = threadIdx.x;
    const int i = blockIdx.x * 256 + tid;              // 512 x 256
    hist[tid] = 0; hist[tid + 256] = 0;
    __syncthreads();
    unsigned long long key = g_minkey[i];
    int code = (int)(key & 0xFFFFFFFFu);
    float dmin = fdec((unsigned)(key >> 32));
    out[OFF_IDX + i] = (float)code;
    g_idx[i] = code;
    atomicAdd(&hist[code], 1);
    red[tid] = g_xnorm[i] + dmin;
    __syncthreads();
    for (int s = 128; s > 0; s >>= 1) {
        if (tid < s) red[tid] += red[tid + s];
        __syncthreads();
    }
    if (tid == 0) atomicAdd(&g_loss, red[0]);
    if (hist[tid]) atomicAdd(&g_counts[tid], hist[tid]);
    if (hist[tid + 256]) atomicAdd(&g_counts[tid + 256], hist[tid + 256]);
}

// ---------------- K: quantized gather ----------------
__global__ void k_gather(const float* __restrict__ emb, float* __restrict__ out) {
    __shared__ int idxs[128];
    const int tid = threadIdx.x, blk = blockIdx.x;     // 1024 x 256
    const int b = blk >> 5, s0 = (blk & 31) << 7;
    if (tid < 128) idxs[tid] = g_idx[blk * 128 + tid];
    __syncthreads();
    for (int i = tid; i < 16384; i += 256) {
        int d = i >> 7, r = i & 127;
        out[OFF_Q + (size_t)b * ZSTRB + (size_t)d * HW + s0 + r] = emb[d * KCODES + idxs[r]];
    }
}

// ---------------- K: cluster-size EMA + smoothing ----------------
__global__ void k_stats(const float* __restrict__ cs_in, float* __restrict__ out) {
    __shared__ float sh[KCODES];
    int k = threadIdx.x;                               // 512
    float ncs = cs_in[k] * 0.99f + 0.01f * (float)g_counts[k];
    out[OFF_CS + k] = ncs;
    sh[k] = ncs;
    __syncthreads();
    for (int s = 256; s > 0; s >>= 1) {
        if (k < s) sh[k] += sh[k + s];
        __syncthreads();
    }
    float n = fmaxf(sh[0], 1e-5f);
    g_cs[k] = (ncs + 1e-5f) / (n + KCODES * 1e-5f) * n;
}

// ---------------- K: embed_sum (shared privatized bins) ----------------
__global__ void k_esum(const float* __restrict__ z) {
    __shared__ float accs[KCODES];
    const int d = blockIdx.x, c = blockIdx.y;
    const int tid = threadIdx.x;                       // 256
    accs[tid] = 0.f; accs[tid + 256] = 0.f;
    __syncthreads();
    const float* zp = z + (size_t)c * ZSTRB + (size_t)d * HW;
    const int* ip = g_idx + c * HW;
    for (int i = tid; i < HW; i += 256)
        atomicAdd(&accs[ip[i]], zp[i]);
    __syncthreads();
    float v0 = accs[tid], v1 = accs[tid + 256];
    if (v0 != 0.f) atomicAdd(&g_embed_sum[d * KCODES + tid], v0);
    if (v1 != 0.f) atomicAdd(&g_embed_sum[d * KCODES + tid + 256], v1);
}

// ---------------- K: finalize ----------------
__global__ void k_final(const float* __restrict__ ea_in, float* __restrict__ out) {
    int i = blockIdx.x * 256 + threadIdx.x;            // 256 x 256
    float ea = ea_in[i] * 0.99f + 0.01f * g_embed_sum[i];
    out[OFF_EA + i] = ea;
    out[OFF_EMB + i] = ea / g_cs[i & (KCODES - 1)];
    if (i == 0) out[OFF_LOSS] = 1.25f * g_loss * (1.f / 16777216.f);
}

extern "C" void kernel_launch(void* const* d_in, const int* in_sizes, int n_in,
                              void* d_out, int out_size) {
    const float* z   = (const float*)d_in[0];
    const float* emb = (const float*)d_in[1];
    const float* cs  = (const float*)d_in[2];
    const float* ea  = (const float*)d_in[3];
    float* out = (float*)d_out;

    cudaFuncSetAttribute(k_gemm, cudaFuncAttributeMaxDynamicSharedMemorySize, SM_GEMM);
    cudaFuncSetAttribute(k_asplit, cudaFuncAttributeMaxDynamicSharedMemorySize, 66048);

    k_zero<<<256, 256>>>();
    k_bsplit<<<128, 512>>>(emb);
    k_enorm<<<2, 256>>>(emb);
    k_asplit<<<1024, 256, 66048>>>(z);
    k_gemm<<<2048, 512, SM_GEMM>>>();
    k_pick<<<512, 256>>>();
    k_fixup<<<64, 512>>>(z, emb);
    k_decode<<<512, 256>>>(out);
    k_gather<<<1024, 256>>>(emb, out);
    k_stats<<<1, 512>>>(cs, out);
    k_esum<<<dim3(128, 32), 256>>>(z);
    k_final<<<256, 256>>>(ea, out);
}